// round 3
// baseline (speedup 1.0000x reference)
#include <cuda_runtime.h>
#include <math.h>

#define N_TOT 65536      // B(64) * C(1024) columns
#define S_DIM 576
#define H_DIM 72

// ---------------- scratch (device globals; no allocation allowed) ----------
__device__ float g_H1[H_DIM * N_TOT];          // 18.9 MB
__device__ float g_Y [H_DIM * N_TOT];          // 18.9 MB
__device__ float g_H2[H_DIM * N_TOT];          // 18.9 MB
__device__ float g_xm[N_TOT];
__device__ float g_attn[128 * 512 * 512];      // 134 MB (B*2 blocks of 512x512)
__device__ float g_out2[S_DIM * N_TOT];        // 151 MB
__device__ float g_M[H_DIM * H_DIM];
__device__ float g_yb[H_DIM];
__device__ float g_w2m[H_DIM];
__device__ float g_b2m;
__device__ float g_mu[S_DIM];
__device__ float g_rstd[S_DIM];

// ---------------- K0: tiny precompute  M = W3@W2, yb = W3@b2, w2m, b2m -----
__global__ void k0_prep(const float* __restrict__ W2,   // (576,72)
                        const float* __restrict__ b2,   // (576)
                        const float* __restrict__ W3)   // (72,576)
{
    __shared__ float row[S_DIM];
    int o = blockIdx.x;
    if (o < H_DIM) {
        for (int e = threadIdx.x; e < S_DIM; e += blockDim.x) row[e] = W3[o * S_DIM + e];
        __syncthreads();
        if (threadIdx.x < H_DIM) {
            int j = threadIdx.x;
            float a = 0.f;
            for (int s = 0; s < S_DIM; s++) a = fmaf(row[s], W2[s * H_DIM + j], a);
            g_M[o * H_DIM + j] = a;
        }
        if (threadIdx.x == H_DIM) {
            float a = 0.f;
            for (int s = 0; s < S_DIM; s++) a = fmaf(row[s], b2[s], a);
            g_yb[o] = a;
        }
    } else {
        if (threadIdx.x < H_DIM) {
            int j = threadIdx.x;
            float a = 0.f;
            for (int s = 0; s < S_DIM; s++) a += W2[s * H_DIM + j];
            g_w2m[j] = a * (1.f / (float)S_DIM);
        }
        if (threadIdx.x == H_DIM) {
            float a = 0.f;
            for (int s = 0; s < S_DIM; s++) a += b2[s];
            g_b2m = a * (1.f / (float)S_DIM);
        }
    }
}

// ---------------- K1: fused gather + H1 = relu(W1 @ x_v + b1) --------------
// grid 2048 (32 columns each), block 256 = (32 nl) x (8 o-groups of 9)
__global__ void __launch_bounds__(256) k1_gather_gemm1(
    const float* __restrict__ x, const float* __restrict__ W1,
    const float* __restrict__ b1)
{
    __shared__ float xt[96 * 33];          // [sl][nl] padded
    __shared__ float wt[72 * 96];          // [o][sl]
    int n0 = blockIdx.x * 32;
    int B  = n0 >> 10;
    int c0 = n0 & 1023;
    int b = B & 15, chunk = B >> 4;
    int ty = (chunk >> 1) * 24, tx = (chunk & 1) * 24;
    int tid = threadIdx.x;
    int nl = tid & 31, og = tid >> 5;

    const float* xb = x + (b * 1024 + c0) * 2304 + ty * 48 + tx;

    float acc[9];
#pragma unroll
    for (int k = 0; k < 9; k++) acc[k] = 0.f;

    for (int t = 0; t < 6; t++) {
        for (int e = tid; e < 96 * 32; e += 256) {
            int cl = e / 96, sl = e - cl * 96;
            int s = t * 96 + sl;
            int si = s / 24, sj = s - si * 24;
            xt[sl * 33 + cl] = xb[cl * 2304 + si * 48 + sj];
        }
        for (int e = tid; e < 72 * 96; e += 256) {
            int o = e / 96, sl = e - o * 96;
            wt[e] = W1[o * S_DIM + t * 96 + sl];
        }
        __syncthreads();
#pragma unroll 4
        for (int sl = 0; sl < 96; sl++) {
            float xv = xt[sl * 33 + nl];
#pragma unroll
            for (int k = 0; k < 9; k++)
                acc[k] = fmaf(wt[(og * 9 + k) * 96 + sl], xv, acc[k]);
        }
        __syncthreads();
    }
#pragma unroll
    for (int k = 0; k < 9; k++) {
        int o = og * 9 + k;
        g_H1[o * N_TOT + n0 + nl] = fmaxf(acc[k] + b1[o], 0.f);
    }
}

// ---------------- K2: Y = M@H1 + yb ;  x_m = w2m@H1 + b2m ------------------
// grid 256, block 256: one column per thread
__global__ void __launch_bounds__(256) k2_Y_xm(void)
{
    __shared__ float Ms[H_DIM * H_DIM];
    __shared__ float ybs[H_DIM], w2ms[H_DIM];
    int tid = threadIdx.x;
    for (int e = tid; e < H_DIM * H_DIM; e += 256) Ms[e] = g_M[e];
    if (tid < H_DIM) { ybs[tid] = g_yb[tid]; w2ms[tid] = g_w2m[tid]; }
    __syncthreads();

    int n = blockIdx.x * 256 + tid;
    float h[H_DIM];
#pragma unroll
    for (int p = 0; p < H_DIM; p++) h[p] = g_H1[p * N_TOT + n];

    float xm = g_b2m;
#pragma unroll
    for (int p = 0; p < H_DIM; p++) xm = fmaf(w2ms[p], h[p], xm);
    g_xm[n] = xm;

    for (int o = 0; o < H_DIM; o++) {
        float a = ybs[o];
#pragma unroll
        for (int p = 0; p < H_DIM; p++) a = fmaf(Ms[o * H_DIM + p], h[p], a);
        g_Y[o * N_TOT + n] = a;
    }
}

// ---------------- K3: attn softmax (max is always 0: diag score = 0) -------
// grid 128 (B*2+blk), block 512: one output column d per thread
__global__ void __launch_bounds__(512) k3_attn(void)
{
    __shared__ float xs[512];
    int g = blockIdx.x;
    int d = threadIdx.x;
    xs[d] = g_xm[g * 512 + d];
    __syncthreads();
    float xd = xs[d];
    float sum = 0.f;
    for (int c = 0; c < 512; c++) {
        float df = xs[c] - xd;
        sum += expf(-df * df);
    }
    float inv = 1.f / sum;
    int abase = g * (512 * 512);
    for (int c = 0; c < 512; c++) {
        float df = xs[c] - xd;
        g_attn[abase + c * 512 + d] = expf(-df * df) * inv;
    }
}

// ---------------- K4: H2 = relu(Y @ attn + b3) per (B,blk) -----------------
// grid (4 dtiles, 128 groups), block 256 = (32 dq) x (8 og); 4 d per thread
__global__ void __launch_bounds__(256) k4_H2(const float* __restrict__ b3)
{
    __shared__ float yt[72 * 32];                       // [o][cl]
    __shared__ __align__(16) float at[32 * 128];        // [cl][dl]
    int g = blockIdx.y;
    int d0 = blockIdx.x * 128;
    int nb = g * 512;
    int tid = threadIdx.x;
    int dq = tid & 31, og = tid >> 5;

    float acc[9][4];
#pragma unroll
    for (int k = 0; k < 9; k++)
#pragma unroll
        for (int j = 0; j < 4; j++) acc[k][j] = 0.f;

    int abase = g * (512 * 512) + d0;
    for (int t = 0; t < 16; t++) {
        int c0 = t * 32;
        for (int e = tid; e < 72 * 32; e += 256) {
            int o = e >> 5, cl = e & 31;
            yt[e] = g_Y[o * N_TOT + nb + c0 + cl];
        }
        for (int e = tid; e < 32 * 128; e += 256) {
            int cl = e >> 7, dl = e & 127;
            at[e] = g_attn[abase + (c0 + cl) * 512 + dl];
        }
        __syncthreads();
        for (int cl = 0; cl < 32; cl++) {
            float4 av = *(const float4*)&at[cl * 128 + dq * 4];
#pragma unroll
            for (int k = 0; k < 9; k++) {
                float yv = yt[(og * 9 + k) * 32 + cl];
                acc[k][0] = fmaf(yv, av.x, acc[k][0]);
                acc[k][1] = fmaf(yv, av.y, acc[k][1]);
                acc[k][2] = fmaf(yv, av.z, acc[k][2]);
                acc[k][3] = fmaf(yv, av.w, acc[k][3]);
            }
        }
        __syncthreads();
    }
#pragma unroll
    for (int k = 0; k < 9; k++) {
        int o = og * 9 + k;
        float bb = b3[o];
        float4 v;
        v.x = fmaxf(acc[k][0] + bb, 0.f);
        v.y = fmaxf(acc[k][1] + bb, 0.f);
        v.z = fmaxf(acc[k][2] + bb, 0.f);
        v.w = fmaxf(acc[k][3] + bb, 0.f);
        *(float4*)&g_H2[o * N_TOT + nb + d0 + dq * 4] = v;
    }
}

// ---------------- K5: out2 = W4 @ H2 + b4 ---------------------------------
// grid 128, block 512: one column per thread, W4 resident in smem (166 KB)
__global__ void __launch_bounds__(512) k5_out2(const float* __restrict__ W4,
                                               const float* __restrict__ b4)
{
    extern __shared__ float w4s[];          // 576*72
    __shared__ float b4s[S_DIM];
    int tid = threadIdx.x;
    for (int e = tid; e < S_DIM * H_DIM; e += 512) w4s[e] = W4[e];
    for (int e = tid; e < S_DIM; e += 512) b4s[e] = b4[e];
    __syncthreads();

    int n = blockIdx.x * 512 + tid;
    float h[H_DIM];
#pragma unroll
    for (int p = 0; p < H_DIM; p++) h[p] = g_H2[p * N_TOT + n];

    for (int s = 0; s < S_DIM; s += 2) {
        float a0 = b4s[s], a1 = b4s[s + 1];
        const float* w0 = &w4s[s * H_DIM];
#pragma unroll
        for (int p = 0; p < H_DIM; p++) {
            a0 = fmaf(w0[p], h[p], a0);
            a1 = fmaf(w0[H_DIM + p], h[p], a1);
        }
        g_out2[s * N_TOT + n]       = a0;
        g_out2[(s + 1) * N_TOT + n] = a1;
    }
}

// ---------------- K6: BN stats per s over 65536 ----------------------------
__global__ void __launch_bounds__(256) k6_stats(void)
{
    int s = blockIdx.x;
    const float4* row = (const float4*)(g_out2 + s * N_TOT);
    float sum = 0.f, sq = 0.f;
    for (int i = threadIdx.x; i < N_TOT / 4; i += 256) {
        float4 v = row[i];
        sum += (v.x + v.y) + (v.z + v.w);
        sq  += (v.x * v.x + v.y * v.y) + (v.z * v.z + v.w * v.w);
    }
#pragma unroll
    for (int off = 16; off; off >>= 1) {
        sum += __shfl_down_sync(0xffffffffu, sum, off);
        sq  += __shfl_down_sync(0xffffffffu, sq, off);
    }
    __shared__ float s1[8], s2[8];
    int w = threadIdx.x >> 5, l = threadIdx.x & 31;
    if (l == 0) { s1[w] = sum; s2[w] = sq; }
    __syncthreads();
    if (threadIdx.x == 0) {
        float a = 0.f, c = 0.f;
        for (int i = 0; i < 8; i++) { a += s1[i]; c += s2[i]; }
        float mu = a * (1.f / (float)N_TOT);
        float var = c * (1.f / (float)N_TOT) - mu * mu;
        g_mu[s] = mu;
        g_rstd[s] = rsqrtf(var + 1e-5f);
    }
}

// ---------------- K7: normalize + scatter + residual + relu ----------------
// grid (32 ctiles, 64 B), block 256, dyn smem 576*33*4
__global__ void __launch_bounds__(256) k7_final(
    const float* __restrict__ x, const float* __restrict__ gamma,
    const float* __restrict__ beta, float* __restrict__ out)
{
    extern __shared__ float tile[];         // [s][33]
    int B  = blockIdx.y;
    int c0 = blockIdx.x * 32;
    int n0 = B * 1024 + c0;
    int tid = threadIdx.x;

    for (int e = tid; e < S_DIM * 32; e += 256) {
        int s = e >> 5, cl = e & 31;
        float rs = g_rstd[s], ga = gamma[s];
        float a  = rs * ga * 0.25f;
        float bb = (beta[s] - g_mu[s] * rs * ga) * 0.25f;
        tile[s * 33 + cl] = fmaf(g_out2[s * N_TOT + n0 + cl], a, bb);
    }
    __syncthreads();

    int b = B & 15, chunk = B >> 4;
    int ty = (chunk >> 1) * 24, tx = (chunk & 1) * 24;
    const float* xb = x   + (b * 1024 + c0) * 2304 + ty * 48 + tx;
    float*       ob = out + (b * 1024 + c0) * 2304 + ty * 48 + tx;

    for (int e = tid; e < 32 * S_DIM; e += 256) {
        int c = e / 576, s = e - c * 576;
        int si = s / 24, sj = s - si * 24;
        int addr = c * 2304 + si * 48 + sj;
        ob[addr] = fmaxf(xb[addr] + tile[s * 33 + c], 0.f);
    }
}

// ---------------- host launch ---------------------------------------------
extern "C" void kernel_launch(void* const* d_in, const int* in_sizes, int n_in,
                              void* d_out, int out_size)
{
    const float* x     = (const float*)d_in[0];
    const float* w1    = (const float*)d_in[1];
    const float* b1    = (const float*)d_in[2];
    const float* w2    = (const float*)d_in[3];
    const float* b2    = (const float*)d_in[4];
    const float* w3    = (const float*)d_in[5];
    const float* b3    = (const float*)d_in[6];
    const float* w4    = (const float*)d_in[7];
    const float* b4    = (const float*)d_in[8];
    const float* gamma = (const float*)d_in[9];
    const float* beta  = (const float*)d_in[10];
    float* out = (float*)d_out;

    cudaFuncSetAttribute(k5_out2, cudaFuncAttributeMaxDynamicSharedMemorySize,
                         S_DIM * H_DIM * 4);
    cudaFuncSetAttribute(k7_final, cudaFuncAttributeMaxDynamicSharedMemorySize,
                         S_DIM * 33 * 4);

    k0_prep<<<73, 128>>>(w2, b2, w3);
    k1_gather_gemm1<<<2048, 256>>>(x, w1, b1);
    k2_Y_xm<<<256, 256>>>();
    k3_attn<<<128, 512>>>();
    k4_H2<<<dim3(4, 128), 256>>>(b3);
    k5_out2<<<128, 512, S_DIM * H_DIM * 4>>>(w4, b4);
    k6_stats<<<S_DIM, 256>>>();
    k7_final<<<dim3(32, 64), 256, S_DIM * 33 * 4>>>(x, gamma, beta, out);
}